// round 15
// baseline (speedup 1.0000x reference)
#include <cuda_runtime.h>
#include <cuda_fp16.h>
#include <stdint.h>
#include <math.h>

// ---------------------------------------------------------------------------
// Problem constants
// ---------------------------------------------------------------------------
#define BATCH   4
#define NTOK    4096
#define INCH    1280
#define CDIM    256
#define QKVD    768
#define HEADS   8
#define HD      32
#define CUT     4
#define BLKTOK  1024
#define M_TOTAL (BATCH*NTOK)
#define SCALE_F 0.07905694150420949f   // 160^-0.5
#define C2LOG   (SCALE_F * 1.4426950408889634f)   // SCALE * log2(e)

// ---------------------------------------------------------------------------
// Scratch
// ---------------------------------------------------------------------------
__device__ __half g_h16[M_TOTAL * CDIM];
__device__ __half g_qkv16[M_TOTAL * QKVD];
__device__ __half g_o16[M_TOTAL * CDIM];
__device__ __half g_wdT[CDIM * INCH];
__device__ __half g_wqkvT[QKVD * CDIM];
__device__ __half g_wupT[INCH * CDIM];

// ---------------------------------------------------------------------------
// helpers
// ---------------------------------------------------------------------------
__device__ __forceinline__ void mma_f16(float* d, const uint32_t* a, const uint32_t* b) {
    asm volatile(
        "mma.sync.aligned.m16n8k16.row.col.f32.f16.f16.f32 "
        "{%0,%1,%2,%3}, {%4,%5,%6,%7}, {%8,%9}, {%0,%1,%2,%3};"
        : "+f"(d[0]), "+f"(d[1]), "+f"(d[2]), "+f"(d[3])
        : "r"(a[0]), "r"(a[1]), "r"(a[2]), "r"(a[3]), "r"(b[0]), "r"(b[1]));
}
__device__ __forceinline__ uint32_t smem_u32(const void* p) {
    uint32_t a;
    asm("{ .reg .u64 t; cvta.to.shared.u64 t, %1; cvt.u32.u64 %0, t; }" : "=r"(a) : "l"(p));
    return a;
}
__device__ __forceinline__ void cp_async16(uint32_t dst, const void* src) {
    asm volatile("cp.async.cg.shared.global [%0], [%1], 16;" :: "r"(dst), "l"(src));
}
#define CP_COMMIT() asm volatile("cp.async.commit_group;" ::: "memory")
#define CP_WAIT(n)  asm volatile("cp.async.wait_group %0;" :: "n"(n) : "memory")

__device__ __forceinline__ uint32_t packh2(float lo, float hi) {
    __half2 h = __floats2half2_rn(lo, hi);
    return *(uint32_t*)&h;
}
__device__ __forceinline__ uint32_t h2ex2(uint32_t h2) {
    uint32_t r;
    asm("ex2.approx.f16x2 %0, %1;" : "=r"(r) : "r"(h2));
    return r;
}
__device__ __forceinline__ void ldmx4t(uint32_t& v0, uint32_t& v1, uint32_t& v2,
                                       uint32_t& v3, uint32_t addr) {
    asm volatile("ldmatrix.sync.aligned.m8n8.x4.trans.shared.b16 {%0,%1,%2,%3}, [%4];"
                 : "=r"(v0), "=r"(v1), "=r"(v2), "=r"(v3) : "r"(addr));
}

// ---------------------------------------------------------------------------
// Fused weight transposes fp32 -> fp16 K-major (one launch, 3 segments)
// ---------------------------------------------------------------------------
__global__ void transpose_all(const float* __restrict__ Wd,
                              const float* __restrict__ Wqkv,
                              const float* __restrict__ Wup,
                              __half* __restrict__ wdT,
                              __half* __restrict__ wqkvT,
                              __half* __restrict__ wupT)
{
    __shared__ float t[32][33];
    const int bx = blockIdx.x;
    const float* W; __half* WT; int K, N, gx, base;
    if (bx < 320)      { W = Wd;   WT = wdT;   K = INCH; N = CDIM; gx = 40; base = 0; }
    else if (bx < 512) { W = Wqkv; WT = wqkvT; K = CDIM; N = QKVD; gx = 8;  base = 320; }
    else               { W = Wup;  WT = wupT;  K = CDIM; N = INCH; gx = 8;  base = 512; }
    const int i = bx - base;
    const int kb = (i % gx) * 32, nb = (i / gx) * 32;
    const int tx = threadIdx.x, ty = threadIdx.y;
#pragma unroll
    for (int r = 0; r < 4; r++)
        t[ty + 8 * r][tx] = W[(size_t)(kb + ty + 8 * r) * N + nb + tx];
    __syncthreads();
#pragma unroll
    for (int r = 0; r < 4; r++)
        WT[(size_t)(nb + ty + 8 * r) * K + kb + tx] = __float2half_rn(t[tx][ty + 8 * r]);
}

// ---------------------------------------------------------------------------
// GEMM1: h16[M,256] = x(fp32)[M,1280] @ WdT(fp16)[256,1280]^T  (proven R9/R10)
// ---------------------------------------------------------------------------
#define A1STRIDE 36
#define A1BUF (128 * A1STRIDE)
#define B1BUF (256 * 16)
#define G1_SMEM_BYTES (3 * (A1BUF + B1BUF) * 4)

__global__ void __launch_bounds__(256, 1)
gemm1_f16(const float* __restrict__ A, const __half* __restrict__ BT,
          __half* __restrict__ C)
{
    extern __shared__ uint32_t smem[];
    float*    As = (float*)smem;
    uint32_t* Bs = smem + 3 * A1BUF;

    const int tid  = threadIdx.x;
    const int wid  = tid >> 5;
    const int lane = tid & 31;
    const int gid  = lane >> 2;
    const int tig  = lane & 3;
    const int wm   = wid >> 2;
    const int wn   = wid & 3;
    const int rowBase = blockIdx.x * 128;
    const int K = INCH, N = CDIM;

    float acc[4][8][4];
#pragma unroll
    for (int mi = 0; mi < 4; mi++)
#pragma unroll
        for (int ni = 0; ni < 8; ni++)
#pragma unroll
            for (int r = 0; r < 4; r++) acc[mi][ni][r] = 0.0f;

    const uint32_t asBase = smem_u32(As);
    const uint32_t bsBase = smem_u32(Bs);
    const int nst = K / 32;

    auto issue = [&](int st, int sb) {
        const int kt = st * 32;
        const uint32_t ab = asBase + (sb * A1BUF) * 4;
        const uint32_t bb = bsBase + (sb * B1BUF) * 4;
#pragma unroll
        for (int it = 0; it < 4; it++) {
            const int ch = tid + 256 * it;
            const int ar = ch >> 3, ag = ch & 7;
            cp_async16(ab + (ar * A1STRIDE + ag * 4) * 4,
                       &A[(size_t)(rowBase + ar) * K + kt + ag * 4]);
            const int br = ch >> 2, bg = ch & 3;
            cp_async16(bb + (br * 16 + bg * 4) * 4,
                       &BT[(size_t)br * K + kt + bg * 8]);
        }
        CP_COMMIT();
    };

    issue(0, 0);
    issue(1, 1);

    int rb = 0;
    for (int st = 0; st < nst; st++) {
        if (st + 1 < nst) { CP_WAIT(1); } else { CP_WAIT(0); }
        __syncthreads();
        if (st + 2 < nst) issue(st + 2, (rb + 2 >= 3) ? rb - 1 : rb + 2);

        const float* Ab = As + rb * A1BUF;
        const uint4* B4 = (const uint4*)(Bs + rb * B1BUF);

        uint4 a0[4], a1[4];
#pragma unroll
        for (int mi = 0; mi < 4; mi++) {
            const int r0 = wm * 64 + mi * 16 + gid;
            const float4 f0 = *(const float4*)(Ab + r0 * A1STRIDE + tig * 8);
            const float4 f1 = *(const float4*)(Ab + r0 * A1STRIDE + tig * 8 + 4);
            const float4 g0 = *(const float4*)(Ab + (r0 + 8) * A1STRIDE + tig * 8);
            const float4 g1 = *(const float4*)(Ab + (r0 + 8) * A1STRIDE + tig * 8 + 4);
            a0[mi].x = packh2(f0.x, f0.y); a0[mi].y = packh2(f0.z, f0.w);
            a0[mi].z = packh2(f1.x, f1.y); a0[mi].w = packh2(f1.z, f1.w);
            a1[mi].x = packh2(g0.x, g0.y); a1[mi].y = packh2(g0.z, g0.w);
            a1[mi].z = packh2(g1.x, g1.y); a1[mi].w = packh2(g1.z, g1.w);
        }
#pragma unroll
        for (int ni = 0; ni < 8; ni++) {
            const int c0 = wn * 64 + ni * 8 + gid;
            const uint4 bv = B4[c0 * 4 + tig];
#pragma unroll
            for (int mi = 0; mi < 4; mi++) {
                uint32_t af[4], bf[2];
                af[0] = a0[mi].x; af[1] = a1[mi].x;
                af[2] = a0[mi].y; af[3] = a1[mi].y;
                bf[0] = bv.x; bf[1] = bv.y;
                mma_f16(acc[mi][ni], af, bf);
                af[0] = a0[mi].z; af[1] = a1[mi].z;
                af[2] = a0[mi].w; af[3] = a1[mi].w;
                bf[0] = bv.z; bf[1] = bv.w;
                mma_f16(acc[mi][ni], af, bf);
            }
        }
        rb = (rb + 1 == 3) ? 0 : rb + 1;
    }

#pragma unroll
    for (int mi = 0; mi < 4; mi++) {
#pragma unroll
        for (int ni = 0; ni < 8; ni++) {
            const int row0 = rowBase + wm * 64 + mi * 16 + gid;
            const int col  = wn * 64 + ni * 8 + tig * 2;
            *(uint32_t*)&C[(size_t)row0 * N + col] = packh2(acc[mi][ni][0], acc[mi][ni][1]);
            *(uint32_t*)&C[(size_t)(row0 + 8) * N + col] = packh2(acc[mi][ni][2], acc[mi][ni][3]);
        }
    }
}

// ---------------------------------------------------------------------------
// Persistent fp16 GEMM v3: cross-tile stage streaming.
// One global stage stream (stage s -> tile s/nst, k-slice s%nst); the 3-slot
// cp.async ring never drains across tile boundaries, epilogue overlaps with
// the next tile's in-flight loads. 256 threads, 8 warps (2x4), warp 64x32.
// ---------------------------------------------------------------------------
#define GB32  16
#define GBUFU (128 * GB32)
#define GEMM_SMEM_BYTES (6 * GBUFU * 4)

template<bool OUT_HALF>
__global__ void __launch_bounds__(256, 2)
gemm_f16(const __half* __restrict__ A, const __half* __restrict__ BT,
         const float* __restrict__ bias, void* __restrict__ Cv,
         int M, int N, int K)
{
    extern __shared__ uint32_t smem[];

    const int tid  = threadIdx.x;
    const int wid  = tid >> 5;
    const int lane = tid & 31;
    const int gid  = lane >> 2;
    const int tig  = lane & 3;
    const int wm   = wid >> 2;
    const int wn   = wid & 3;

    const int fr = tid >> 2;
    const int fg = tid & 3;
    const uint32_t sBase = smem_u32(smem);
    const int nst = K / 32;
    const int nTX = N / 128;
    const int nTiles = nTX * (M / 128);

    const int myTiles = (nTiles - (int)blockIdx.x + (int)gridDim.x - 1) / (int)gridDim.x;
    if (myTiles <= 0) return;
    const int total = myTiles * nst;

    auto issue = [&](int s, int sb) {
        const int tile = blockIdx.x + (s / nst) * gridDim.x;
        const int rB = (tile / nTX) * 128;
        const int cB = (tile % nTX) * 128;
        const int kt = (s % nst) * 32;
        const uint32_t ab = sBase + (sb * 2 * GBUFU) * 4;
        const uint32_t bb = ab + GBUFU * 4;
#pragma unroll
        for (int it = 0; it < 2; it++) {
            const int r = fr + 64 * it;
            cp_async16(ab + (r * GB32 + fg * 4) * 4,
                       &A[(size_t)(rB + r) * K + kt + fg * 8]);
            cp_async16(bb + (r * GB32 + fg * 4) * 4,
                       &BT[(size_t)(cB + r) * K + kt + fg * 8]);
        }
        CP_COMMIT();
    };

    issue(0, 0);
    if (total > 1) issue(1, 1);

    float acc[4][4][4];
#pragma unroll
    for (int mi = 0; mi < 4; mi++)
#pragma unroll
        for (int ni = 0; ni < 4; ni++)
#pragma unroll
            for (int r = 0; r < 4; r++) acc[mi][ni][r] = 0.0f;

    int rb = 0;
    for (int s = 0; s < total; s++) {
        if (s + 1 < total) { CP_WAIT(1); } else { CP_WAIT(0); }
        __syncthreads();
        if (s + 2 < total) issue(s + 2, (rb + 2 >= 3) ? rb - 1 : rb + 2);

        const uint4* A4 = (const uint4*)(smem + rb * 2 * GBUFU);
        const uint4* B4 = (const uint4*)(smem + rb * 2 * GBUFU + GBUFU);

        uint4 bv[4];
#pragma unroll
        for (int ni = 0; ni < 4; ni++)
            bv[ni] = B4[(wn * 32 + ni * 8 + gid) * 4 + tig];
#pragma unroll
        for (int mi = 0; mi < 4; mi++) {
            const int r0 = wm * 64 + mi * 16 + gid;
            const uint4 a0 = A4[r0 * 4 + tig];
            const uint4 a1 = A4[(r0 + 8) * 4 + tig];
#pragma unroll
            for (int ni = 0; ni < 4; ni++) {
                uint32_t af[4], bf[2];
                af[0] = a0.x; af[1] = a1.x;
                af[2] = a0.y; af[3] = a1.y;
                bf[0] = bv[ni].x; bf[1] = bv[ni].y;
                mma_f16(acc[mi][ni], af, bf);
                af[0] = a0.z; af[1] = a1.z;
                af[2] = a0.w; af[3] = a1.w;
                bf[0] = bv[ni].z; bf[1] = bv[ni].w;
                mma_f16(acc[mi][ni], af, bf);
            }
        }

        // ---- tile finished: epilogue overlaps with next tile's loads
        if ((s % nst) == nst - 1) {
            const int tile = blockIdx.x + (s / nst) * gridDim.x;
            const int rowBase = (tile / nTX) * 128;
            const int colBase = (tile % nTX) * 128;
#pragma unroll
            for (int mi = 0; mi < 4; mi++) {
#pragma unroll
                for (int ni = 0; ni < 4; ni++) {
                    const int row0 = rowBase + wm * 64 + mi * 16 + gid;
                    const int col  = colBase + wn * 32 + ni * 8 + tig * 2;
                    if (OUT_HALF) {
                        __half* C = (__half*)Cv;
                        *(uint32_t*)&C[(size_t)row0 * N + col] =
                            packh2(acc[mi][ni][0], acc[mi][ni][1]);
                        *(uint32_t*)&C[(size_t)(row0 + 8) * N + col] =
                            packh2(acc[mi][ni][2], acc[mi][ni][3]);
                    } else {
                        float* C = (float*)Cv;
                        float b0 = 0.f, b1 = 0.f;
                        if (bias) { b0 = bias[col]; b1 = bias[col + 1]; }
                        float2 v0, v1;
                        v0.x = acc[mi][ni][0] + b0; v0.y = acc[mi][ni][1] + b1;
                        v1.x = acc[mi][ni][2] + b0; v1.y = acc[mi][ni][3] + b1;
                        *(float2*)&C[(size_t)row0 * N + col] = v0;
                        *(float2*)&C[(size_t)(row0 + 8) * N + col] = v1;
                    }
#pragma unroll
                    for (int r = 0; r < 4; r++) acc[mi][ni][r] = 0.0f;
                }
            }
        }
        rb = (rb + 1 == 3) ? 0 : rb + 1;
    }
}

// ---------------------------------------------------------------------------
// fp16 flash attention v4 (proven R14, 49.2us): no online max, direct ex2.
// ---------------------------------------------------------------------------
__global__ void __launch_bounds__(128, 2)
attn_f16(const __half* __restrict__ qkv, __half* __restrict__ o_out)
{
    __shared__ uint4 sk4[3][256];
    __shared__ uint4 sv4[3][256];

    const int bx = blockIdx.x;
    const int qt = bx & 7;
    const int c  = (bx >> 3) & 3;
    const int h  = (bx >> 5) & 7;
    const int b  = bx >> 8;

    const int tid  = threadIdx.x;
    const int wid  = tid >> 5;
    const int lane = tid & 31;
    const int gid  = lane >> 2;
    const int tig  = lane & 3;

    const size_t rowbase = (size_t)b * NTOK + (size_t)c * BLKTOK;
    const int q0 = qt * 128 + wid * 32;

    uint4 qa[2][2];
#pragma unroll
    for (int mt = 0; mt < 2; mt++) {
        const __half* qp0 = qkv + (rowbase + q0 + mt * 16 + gid) * QKVD + h * HD;
        const __half* qp1 = qkv + (rowbase + q0 + mt * 16 + gid + 8) * QKVD + h * HD;
        qa[mt][0] = *(const uint4*)(qp0 + 8 * tig);
        qa[mt][1] = *(const uint4*)(qp1 + 8 * tig);
    }

    const int key0 = ((lane >> 3) & 1) * 8 + (lane & 7);
    const int csw  = (key0 >> 1) & 3;
    const int csel = (lane >> 4) & 1;

    const uint32_t skaddr = smem_u32(sk4);
    const uint32_t svaddr = smem_u32(sv4);

    auto issue = [&](int t, int sb) {
#pragma unroll
        for (int it = 0; it < 2; it++) {
            const int idx = tid + 128 * it;
            const int k = idx >> 2, g = idx & 3;
            const __half* base = qkv + (rowbase + t * 64 + k) * QKVD + CDIM + h * HD;
            cp_async16(skaddr + (sb * 256 + k * 4 + g) * 16, base + g * 8);
            cp_async16(svaddr + (sb * 256 + k * 4 + (g ^ ((k >> 1) & 3))) * 16,
                       base + CDIM + g * 8);
        }
        CP_COMMIT();
    };

    issue(0, 0);
    issue(1, 1);

    float lacc[2][4];
    float o[2][4][4];
#pragma unroll
    for (int mt = 0; mt < 2; mt++) {
#pragma unroll
        for (int r = 0; r < 4; r++) lacc[mt][r] = 0.0f;
#pragma unroll
        for (int ni = 0; ni < 4; ni++)
#pragma unroll
            for (int r = 0; r < 4; r++) o[mt][ni][r] = 0.0f;
    }

    const uint32_t ONES = 0x3C003C00u;

    int rb = 0;
    for (int kt = 0; kt < 16; kt++) {
        if (kt + 1 < 16) { CP_WAIT(1); } else { CP_WAIT(0); }
        __syncthreads();
        if (kt + 2 < 16) issue(kt + 2, (rb + 2 >= 3) ? rb - 1 : rb + 2);

        uint4 kb[8];
#pragma unroll
        for (int nj = 0; nj < 8; nj++)
            kb[nj] = sk4[rb][(nj * 8 + gid) * 4 + tig];

        uint32_t pf[2][8][2];
#pragma unroll
        for (int mt = 0; mt < 2; mt++) {
#pragma unroll
            for (int nj = 0; nj < 8; nj++) {
                float s[4];
#pragma unroll
                for (int r = 0; r < 4; r++) s[r] = 0.0f;
                uint32_t af[4], bf[2];
                af[0] = qa[mt][0].x; af[1] = qa[mt][1].x;
                af[2] = qa[mt][0].y; af[3] = qa[mt][1].y;
                bf[0] = kb[nj].x; bf[1] = kb[nj].y;
                mma_f16(s, af, bf);
                af[0] = qa[mt][0].z; af[1] = qa[mt][1].z;
                af[2] = qa[mt][0].w; af[3] = qa[mt][1].w;
                bf[0] = kb[nj].z; bf[1] = kb[nj].w;
                mma_f16(s, af, bf);
                pf[mt][nj][0] = h2ex2(packh2(s[0] * C2LOG, s[1] * C2LOG));
                pf[mt][nj][1] = h2ex2(packh2(s[2] * C2LOG, s[3] * C2LOG));
            }
        }

        const uint32_t vbase = svaddr + rb * 4096 + key0 * 64;
#pragma unroll
        for (int t = 0; t < 4; t++) {
            uint32_t af[2][4];
#pragma unroll
            for (int mt = 0; mt < 2; mt++) {
                af[mt][0] = pf[mt][2 * t][0];
                af[mt][1] = pf[mt][2 * t][1];
                af[mt][2] = pf[mt][2 * t + 1][0];
                af[mt][3] = pf[mt][2 * t + 1][1];
            }
            uint32_t ob[2] = { ONES, ONES };
            mma_f16(lacc[0], af[0], ob);
            mma_f16(lacc[1], af[1], ob);
#pragma unroll
            for (int dh = 0; dh < 2; dh++) {
                uint32_t v0, v1, v2, v3;
                const uint32_t addr = vbase + t * 1024 + (((dh * 2 + csel) ^ csw) * 16);
                ldmx4t(v0, v1, v2, v3, addr);
                uint32_t bf0[2] = { v0, v1 };
                uint32_t bf1[2] = { v2, v3 };
#pragma unroll
                for (int mt = 0; mt < 2; mt++) {
                    mma_f16(o[mt][dh * 2],     af[mt], bf0);
                    mma_f16(o[mt][dh * 2 + 1], af[mt], bf1);
                }
            }
        }
        rb = (rb + 1 == 3) ? 0 : rb + 1;
    }

#pragma unroll
    for (int mt = 0; mt < 2; mt++) {
        const float inv0 = 1.0f / lacc[mt][0];
        const float inv1 = 1.0f / lacc[mt][2];
        __half* op0 = o_out + (rowbase + q0 + mt * 16 + gid) * CDIM + h * HD;
        __half* op1 = o_out + (rowbase + q0 + mt * 16 + gid + 8) * CDIM + h * HD;
#pragma unroll
        for (int ni = 0; ni < 4; ni++) {
            *(uint32_t*)(op0 + ni * 8 + tig * 2) =
                packh2(o[mt][ni][0] * inv0, o[mt][ni][1] * inv0);
            *(uint32_t*)(op1 + ni * 8 + tig * 2) =
                packh2(o[mt][ni][2] * inv1, o[mt][ni][3] * inv1);
        }
    }
}

// ---------------------------------------------------------------------------
// Launch
// ---------------------------------------------------------------------------
extern "C" void kernel_launch(void* const* d_in, const int* in_sizes, int n_in,
                              void* d_out, int out_size)
{
    const float* x    = (const float*)d_in[0];
    const float* Wd   = (const float*)d_in[1];
    const float* Wqkv = (const float*)d_in[2];
    const float* Wup  = (const float*)d_in[3];
    const float* bup  = (const float*)d_in[4];
    float* out = (float*)d_out;

    __half *ph16, *pqkv16, *po16, *pwdT, *pwqkvT, *pwupT;
    cudaGetSymbolAddress((void**)&ph16,   g_h16);
    cudaGetSymbolAddress((void**)&pqkv16, g_qkv16);
    cudaGetSymbolAddress((void**)&po16,   g_o16);
    cudaGetSymbolAddress((void**)&pwdT,   g_wdT);
    cudaGetSymbolAddress((void**)&pwqkvT, g_wqkvT);
    cudaGetSymbolAddress((void**)&pwupT,  g_wupT);

    cudaFuncSetAttribute(gemm1_f16, cudaFuncAttributeMaxDynamicSharedMemorySize,
                         G1_SMEM_BYTES);
    cudaFuncSetAttribute(gemm_f16<true>,
                         cudaFuncAttributeMaxDynamicSharedMemorySize, GEMM_SMEM_BYTES);
    cudaFuncSetAttribute(gemm_f16<false>,
                         cudaFuncAttributeMaxDynamicSharedMemorySize, GEMM_SMEM_BYTES);

    transpose_all<<<832, dim3(32, 8)>>>(Wd, Wqkv, Wup, pwdT, pwqkvT, pwupT);

    gemm1_f16<<<M_TOTAL / 128, 256, G1_SMEM_BYTES>>>(x, pwdT, ph16);

    gemm_f16<true><<<296, 256, GEMM_SMEM_BYTES>>>(ph16, pwqkvT, nullptr, pqkv16,
                                                  M_TOTAL, QKVD, CDIM);

    attn_f16<<<BATCH * HEADS * CUT * (BLKTOK / 128), 128>>>(pqkv16, po16);

    gemm_f16<false><<<296, 256, GEMM_SMEM_BYTES>>>(po16, pwupT, bup, out,
                                                   M_TOTAL, INCH, CDIM);
}

// round 16
// speedup vs baseline: 1.0585x; 1.0585x over previous
#include <cuda_runtime.h>
#include <cuda_fp16.h>
#include <stdint.h>
#include <math.h>

// ---------------------------------------------------------------------------
// Problem constants
// ---------------------------------------------------------------------------
#define BATCH   4
#define NTOK    4096
#define INCH    1280
#define CDIM    256
#define QKVD    768
#define HEADS   8
#define HD      32
#define CUT     4
#define BLKTOK  1024
#define M_TOTAL (BATCH*NTOK)
#define SCALE_F 0.07905694150420949f   // 160^-0.5
#define C2LOG   (SCALE_F * 1.4426950408889634f)   // SCALE * log2(e)

// ---------------------------------------------------------------------------
// Scratch
// ---------------------------------------------------------------------------
__device__ __half g_qkv16[M_TOTAL * QKVD];
__device__ __half g_o16[M_TOTAL * CDIM];
__device__ __half g_wdT[CDIM * INCH];
__device__ __half g_wqkvT[QKVD * CDIM];
__device__ __half g_wupT[INCH * CDIM];

// ---------------------------------------------------------------------------
// helpers
// ---------------------------------------------------------------------------
__device__ __forceinline__ void mma_f16(float* d, const uint32_t* a, const uint32_t* b) {
    asm volatile(
        "mma.sync.aligned.m16n8k16.row.col.f32.f16.f16.f32 "
        "{%0,%1,%2,%3}, {%4,%5,%6,%7}, {%8,%9}, {%0,%1,%2,%3};"
        : "+f"(d[0]), "+f"(d[1]), "+f"(d[2]), "+f"(d[3])
        : "r"(a[0]), "r"(a[1]), "r"(a[2]), "r"(a[3]), "r"(b[0]), "r"(b[1]));
}
__device__ __forceinline__ uint32_t smem_u32(const void* p) {
    uint32_t a;
    asm("{ .reg .u64 t; cvta.to.shared.u64 t, %1; cvt.u32.u64 %0, t; }" : "=r"(a) : "l"(p));
    return a;
}
__device__ __forceinline__ void cp_async16(uint32_t dst, const void* src) {
    asm volatile("cp.async.cg.shared.global [%0], [%1], 16;" :: "r"(dst), "l"(src));
}
#define CP_COMMIT() asm volatile("cp.async.commit_group;" ::: "memory")
#define CP_WAIT(n)  asm volatile("cp.async.wait_group %0;" :: "n"(n) : "memory")

__device__ __forceinline__ uint32_t packh2(float lo, float hi) {
    __half2 h = __floats2half2_rn(lo, hi);
    return *(uint32_t*)&h;
}
__device__ __forceinline__ uint32_t h2ex2(uint32_t h2) {
    uint32_t r;
    asm("ex2.approx.f16x2 %0, %1;" : "=r"(r) : "r"(h2));
    return r;
}
__device__ __forceinline__ void ldmx4t(uint32_t& v0, uint32_t& v1, uint32_t& v2,
                                       uint32_t& v3, uint32_t addr) {
    asm volatile("ldmatrix.sync.aligned.m8n8.x4.trans.shared.b16 {%0,%1,%2,%3}, [%4];"
                 : "=r"(v0), "=r"(v1), "=r"(v2), "=r"(v3) : "r"(addr));
}

// ---------------------------------------------------------------------------
// Fused weight transposes fp32 -> fp16 K-major (one launch, 3 segments)
// ---------------------------------------------------------------------------
__global__ void transpose_all(const float* __restrict__ Wd,
                              const float* __restrict__ Wqkv,
                              const float* __restrict__ Wup,
                              __half* __restrict__ wdT,
                              __half* __restrict__ wqkvT,
                              __half* __restrict__ wupT)
{
    __shared__ float t[32][33];
    const int bx = blockIdx.x;
    const float* W; __half* WT; int K, N, gx, base;
    if (bx < 320)      { W = Wd;   WT = wdT;   K = INCH; N = CDIM; gx = 40; base = 0; }
    else if (bx < 512) { W = Wqkv; WT = wqkvT; K = CDIM; N = QKVD; gx = 8;  base = 320; }
    else               { W = Wup;  WT = wupT;  K = CDIM; N = INCH; gx = 8;  base = 512; }
    const int i = bx - base;
    const int kb = (i % gx) * 32, nb = (i / gx) * 32;
    const int tx = threadIdx.x, ty = threadIdx.y;
#pragma unroll
    for (int r = 0; r < 4; r++)
        t[ty + 8 * r][tx] = W[(size_t)(kb + ty + 8 * r) * N + nb + tx];
    __syncthreads();
#pragma unroll
    for (int r = 0; r < 4; r++)
        WT[(size_t)(nb + ty + 8 * r) * K + kb + tx] = __float2half_rn(t[tx][ty + 8 * r]);
}

// ---------------------------------------------------------------------------
// Fused GEMM1+GEMM2: per CTA (128 rows):
//   phase1: h(128x256) = x(fp32)@WdT  (proven R9 mainloop), h -> SMEM only
//   phase2: qkv(128x768) = h(smem) @ WqkvT, 6 N-chunks of 128, B streamed
// Smem: phase1 ring 102KB; phase2 overlays: h 64KB + B ring 24KB.
// 256 threads. Phase1 warps 2x4 (64x64), phase2 warps 2x4 (64x32).
// ---------------------------------------------------------------------------
#define A1STRIDE 36
#define A1BUF (128 * A1STRIDE)            // floats per A stage
#define B1BUF (256 * 16)                  // b32 per B stage
#define G1_SMEM_BYTES (3 * (A1BUF + B1BUF) * 4)   // 104448
#define H_WORDS 16384                     // 128x256 fp16 = 16384 b32
#define B2RING  (H_WORDS)                 // ring starts after h (word offset)
#define B2BUF   2048                      // b32 per B2 stage ([128][16])

__global__ void __launch_bounds__(256, 1)
gemm12_f16(const float* __restrict__ A, const __half* __restrict__ BT1,
           const __half* __restrict__ BT2, __half* __restrict__ C)
{
    extern __shared__ uint32_t smem[];
    float*    As = (float*)smem;
    uint32_t* Bs = smem + 3 * A1BUF;

    const int tid  = threadIdx.x;
    const int wid  = tid >> 5;
    const int lane = tid & 31;
    const int gid  = lane >> 2;
    const int tig  = lane & 3;
    const int wm   = wid >> 2;    // 0..1
    const int wn   = wid & 3;     // 0..3
    const int rowBase = blockIdx.x * 128;

    // ======================= PHASE 1: h = x @ Wd =======================
    {
        const int K = INCH;
        float acc[4][8][4];
#pragma unroll
        for (int mi = 0; mi < 4; mi++)
#pragma unroll
            for (int ni = 0; ni < 8; ni++)
#pragma unroll
                for (int r = 0; r < 4; r++) acc[mi][ni][r] = 0.0f;

        const uint32_t asBase = smem_u32(As);
        const uint32_t bsBase = smem_u32(Bs);
        const int nst = K / 32;   // 40

        auto issue = [&](int st, int sb) {
            const int kt = st * 32;
            const uint32_t ab = asBase + (sb * A1BUF) * 4;
            const uint32_t bb = bsBase + (sb * B1BUF) * 4;
#pragma unroll
            for (int it = 0; it < 4; it++) {
                const int ch = tid + 256 * it;
                const int ar = ch >> 3, ag = ch & 7;
                cp_async16(ab + (ar * A1STRIDE + ag * 4) * 4,
                           &A[(size_t)(rowBase + ar) * K + kt + ag * 4]);
                const int br = ch >> 2, bg = ch & 3;
                cp_async16(bb + (br * 16 + bg * 4) * 4,
                           &BT1[(size_t)br * K + kt + bg * 8]);
            }
            CP_COMMIT();
        };

        issue(0, 0);
        issue(1, 1);

        int rb = 0;
        for (int st = 0; st < nst; st++) {
            if (st + 1 < nst) { CP_WAIT(1); } else { CP_WAIT(0); }
            __syncthreads();
            if (st + 2 < nst) issue(st + 2, (rb + 2 >= 3) ? rb - 1 : rb + 2);

            const float* Ab = As + rb * A1BUF;
            const uint4* B4 = (const uint4*)(Bs + rb * B1BUF);

            uint4 a0[4], a1[4];
#pragma unroll
            for (int mi = 0; mi < 4; mi++) {
                const int r0 = wm * 64 + mi * 16 + gid;
                const float4 f0 = *(const float4*)(Ab + r0 * A1STRIDE + tig * 8);
                const float4 f1 = *(const float4*)(Ab + r0 * A1STRIDE + tig * 8 + 4);
                const float4 g0 = *(const float4*)(Ab + (r0 + 8) * A1STRIDE + tig * 8);
                const float4 g1 = *(const float4*)(Ab + (r0 + 8) * A1STRIDE + tig * 8 + 4);
                a0[mi].x = packh2(f0.x, f0.y); a0[mi].y = packh2(f0.z, f0.w);
                a0[mi].z = packh2(f1.x, f1.y); a0[mi].w = packh2(f1.z, f1.w);
                a1[mi].x = packh2(g0.x, g0.y); a1[mi].y = packh2(g0.z, g0.w);
                a1[mi].z = packh2(g1.x, g1.y); a1[mi].w = packh2(g1.z, g1.w);
            }
#pragma unroll
            for (int ni = 0; ni < 8; ni++) {
                const int c0 = wn * 64 + ni * 8 + gid;
                const uint4 bv = B4[c0 * 4 + tig];
#pragma unroll
                for (int mi = 0; mi < 4; mi++) {
                    uint32_t af[4], bf[2];
                    af[0] = a0[mi].x; af[1] = a1[mi].x;
                    af[2] = a0[mi].y; af[3] = a1[mi].y;
                    bf[0] = bv.x; bf[1] = bv.y;
                    mma_f16(acc[mi][ni], af, bf);
                    af[0] = a0[mi].z; af[1] = a1[mi].z;
                    af[2] = a0[mi].w; af[3] = a1[mi].w;
                    bf[0] = bv.z; bf[1] = bv.w;
                    mma_f16(acc[mi][ni], af, bf);
                }
            }
            rb = (rb + 1 == 3) ? 0 : rb + 1;
        }

        // ---- write h into SMEM only (layout [8 kstage][128 row][16 b32])
        __syncthreads();   // all ring reads complete before overlay write
#pragma unroll
        for (int mi = 0; mi < 4; mi++) {
#pragma unroll
            for (int ni = 0; ni < 8; ni++) {
                const int row0 = wm * 64 + mi * 16 + gid;
                const int col  = wn * 64 + ni * 8 + tig * 2;
                const int w    = col >> 1;            // b32 word index 0..127
                const int st   = w >> 4;
                const int wi   = w & 15;
                smem[st * 2048 + row0 * 16 + wi] = packh2(acc[mi][ni][0], acc[mi][ni][1]);
                smem[st * 2048 + (row0 + 8) * 16 + wi] = packh2(acc[mi][ni][2], acc[mi][ni][3]);
            }
        }
    }

    // ======================= PHASE 2: qkv = h @ Wqkv =======================
    {
        const int K = CDIM;   // 256
        const uint32_t ringB = smem_u32(smem + B2RING);

        auto issue2 = [&](int gs, int sb) {
            const int chunk = gs >> 3;        // 0..5
            const int st    = gs & 7;
            const int kt    = st * 32;
            const uint32_t bb = ringB + (sb * B2BUF) * 4;
#pragma unroll
            for (int it = 0; it < 2; it++) {
                const int r = (tid >> 2) + 64 * it;   // B row (qkv col) 0..127
                const int g = tid & 3;
                cp_async16(bb + (r * 16 + g * 4) * 4,
                           &BT2[(size_t)(chunk * 128 + r) * K + kt + g * 8]);
            }
            CP_COMMIT();
        };

        issue2(0, 0);
        issue2(1, 1);

        float acc2[4][4][4];
#pragma unroll
        for (int mi = 0; mi < 4; mi++)
#pragma unroll
            for (int ni = 0; ni < 4; ni++)
#pragma unroll
                for (int r = 0; r < 4; r++) acc2[mi][ni][r] = 0.0f;

        const uint4* hA4 = (const uint4*)smem;   // [8][128][4 uint4]

        int rb = 0;
        for (int gs = 0; gs < 48; gs++) {
            const int chunk = gs >> 3;
            const int st    = gs & 7;
            if (gs + 1 < 48) { CP_WAIT(1); } else { CP_WAIT(0); }
            __syncthreads();   // first iter: h visible; later: ring slot safe
            if (gs + 2 < 48) issue2(gs + 2, (rb + 2 >= 3) ? rb - 1 : rb + 2);

            const uint4* B4 = (const uint4*)(smem + B2RING + rb * B2BUF);

            uint4 bv[4];
#pragma unroll
            for (int ni = 0; ni < 4; ni++)
                bv[ni] = B4[(wn * 32 + ni * 8 + gid) * 4 + tig];
#pragma unroll
            for (int mi = 0; mi < 4; mi++) {
                const int r0 = wm * 64 + mi * 16 + gid;
                const uint4 a0 = hA4[st * 512 + r0 * 4 + tig];
                const uint4 a1 = hA4[st * 512 + (r0 + 8) * 4 + tig];
#pragma unroll
                for (int ni = 0; ni < 4; ni++) {
                    uint32_t af[4], bf[2];
                    af[0] = a0.x; af[1] = a1.x;
                    af[2] = a0.y; af[3] = a1.y;
                    bf[0] = bv[ni].x; bf[1] = bv[ni].y;
                    mma_f16(acc2[mi][ni], af, bf);
                    af[0] = a0.z; af[1] = a1.z;
                    af[2] = a0.w; af[3] = a1.w;
                    bf[0] = bv[ni].z; bf[1] = bv[ni].w;
                    mma_f16(acc2[mi][ni], af, bf);
                }
            }

            if (st == 7) {   // chunk complete: write qkv, reset acc2
#pragma unroll
                for (int mi = 0; mi < 4; mi++) {
#pragma unroll
                    for (int ni = 0; ni < 4; ni++) {
                        const int row0 = rowBase + wm * 64 + mi * 16 + gid;
                        const int col  = chunk * 128 + wn * 32 + ni * 8 + tig * 2;
                        *(uint32_t*)&C[(size_t)row0 * QKVD + col] =
                            packh2(acc2[mi][ni][0], acc2[mi][ni][1]);
                        *(uint32_t*)&C[(size_t)(row0 + 8) * QKVD + col] =
                            packh2(acc2[mi][ni][2], acc2[mi][ni][3]);
#pragma unroll
                        for (int r = 0; r < 4; r++) acc2[mi][ni][r] = 0.0f;
                    }
                }
            }
            rb = (rb + 1 == 3) ? 0 : rb + 1;
        }
    }
}

// ---------------------------------------------------------------------------
// Persistent fp16 GEMM (exact R13/R14 proven version): 256 threads, 8 warps
// (2x4), warp 64x32, per-tile 3-stage cp.async ring.
// ---------------------------------------------------------------------------
#define GB32  16
#define GBUFU (128 * GB32)
#define GEMM_SMEM_BYTES (6 * GBUFU * 4)

template<bool OUT_HALF>
__global__ void __launch_bounds__(256, 2)
gemm_f16(const __half* __restrict__ A, const __half* __restrict__ BT,
         const float* __restrict__ bias, void* __restrict__ Cv,
         int M, int N, int K)
{
    extern __shared__ uint32_t smem[];

    const int tid  = threadIdx.x;
    const int wid  = tid >> 5;
    const int lane = tid & 31;
    const int gid  = lane >> 2;
    const int tig  = lane & 3;
    const int wm   = wid >> 2;
    const int wn   = wid & 3;

    const int fr = tid >> 2;
    const int fg = tid & 3;
    const uint32_t sBase = smem_u32(smem);
    const int nst = K / 32;
    const int nTX = N / 128;
    const int nTiles = nTX * (M / 128);

    for (int tile = blockIdx.x; tile < nTiles; tile += gridDim.x) {
        const int rowBase = (tile / nTX) * 128;
        const int colBase = (tile % nTX) * 128;

        __syncthreads();

        float acc[4][4][4];
#pragma unroll
        for (int mi = 0; mi < 4; mi++)
#pragma unroll
            for (int ni = 0; ni < 4; ni++)
#pragma unroll
                for (int r = 0; r < 4; r++) acc[mi][ni][r] = 0.0f;

        auto issue = [&](int st, int sb) {
            const int kt = st * 32;
            const uint32_t ab = sBase + (sb * 2 * GBUFU) * 4;
            const uint32_t bb = ab + GBUFU * 4;
#pragma unroll
            for (int it = 0; it < 2; it++) {
                const int r = fr + 64 * it;
                cp_async16(ab + (r * GB32 + fg * 4) * 4,
                           &A[(size_t)(rowBase + r) * K + kt + fg * 8]);
                cp_async16(bb + (r * GB32 + fg * 4) * 4,
                           &BT[(size_t)(colBase + r) * K + kt + fg * 8]);
            }
            CP_COMMIT();
        };

        issue(0, 0);
        if (nst > 1) issue(1, 1);

        int rb = 0;
        for (int st = 0; st < nst; st++) {
            if (st + 1 < nst) { CP_WAIT(1); } else { CP_WAIT(0); }
            __syncthreads();
            if (st + 2 < nst) issue(st + 2, (rb + 2 >= 3) ? rb - 1 : rb + 2);

            const uint4* A4 = (const uint4*)(smem + rb * 2 * GBUFU);
            const uint4* B4 = (const uint4*)(smem + rb * 2 * GBUFU + GBUFU);

            uint4 bv[4];
#pragma unroll
            for (int ni = 0; ni < 4; ni++)
                bv[ni] = B4[(wn * 32 + ni * 8 + gid) * 4 + tig];
#pragma unroll
            for (int mi = 0; mi < 4; mi++) {
                const int r0 = wm * 64 + mi * 16 + gid;
                const uint4 a0 = A4[r0 * 4 + tig];
                const uint4 a1 = A4[(r0 + 8) * 4 + tig];
#pragma unroll
                for (int ni = 0; ni < 4; ni++) {
                    uint32_t af[4], bf[2];
                    af[0] = a0.x; af[1] = a1.x;
                    af[2] = a0.y; af[3] = a1.y;
                    bf[0] = bv[ni].x; bf[1] = bv[ni].y;
                    mma_f16(acc[mi][ni], af, bf);
                    af[0] = a0.z; af[1] = a1.z;
                    af[2] = a0.w; af[3] = a1.w;
                    bf[0] = bv[ni].z; bf[1] = bv[ni].w;
                    mma_f16(acc[mi][ni], af, bf);
                }
            }
            rb = (rb + 1 == 3) ? 0 : rb + 1;
        }

#pragma unroll
        for (int mi = 0; mi < 4; mi++) {
#pragma unroll
            for (int ni = 0; ni < 4; ni++) {
                const int row0 = rowBase + wm * 64 + mi * 16 + gid;
                const int col  = colBase + wn * 32 + ni * 8 + tig * 2;
                if (OUT_HALF) {
                    __half* C = (__half*)Cv;
                    *(uint32_t*)&C[(size_t)row0 * N + col] =
                        packh2(acc[mi][ni][0], acc[mi][ni][1]);
                    *(uint32_t*)&C[(size_t)(row0 + 8) * N + col] =
                        packh2(acc[mi][ni][2], acc[mi][ni][3]);
                } else {
                    float* C = (float*)Cv;
                    float b0 = 0.f, b1 = 0.f;
                    if (bias) { b0 = bias[col]; b1 = bias[col + 1]; }
                    float2 v0, v1;
                    v0.x = acc[mi][ni][0] + b0; v0.y = acc[mi][ni][1] + b1;
                    v1.x = acc[mi][ni][2] + b0; v1.y = acc[mi][ni][3] + b1;
                    *(float2*)&C[(size_t)row0 * N + col] = v0;
                    *(float2*)&C[(size_t)(row0 + 8) * N + col] = v1;
                }
            }
        }
    }
}

// ---------------------------------------------------------------------------
// fp16 flash attention v4 (exact R14 proven version, 49.2us)
// ---------------------------------------------------------------------------
__global__ void __launch_bounds__(128, 2)
attn_f16(const __half* __restrict__ qkv, __half* __restrict__ o_out)
{
    __shared__ uint4 sk4[3][256];
    __shared__ uint4 sv4[3][256];

    const int bx = blockIdx.x;
    const int qt = bx & 7;
    const int c  = (bx >> 3) & 3;
    const int h  = (bx >> 5) & 7;
    const int b  = bx >> 8;

    const int tid  = threadIdx.x;
    const int wid  = tid >> 5;
    const int lane = tid & 31;
    const int gid  = lane >> 2;
    const int tig  = lane & 3;

    const size_t rowbase = (size_t)b * NTOK + (size_t)c * BLKTOK;
    const int q0 = qt * 128 + wid * 32;

    uint4 qa[2][2];
#pragma unroll
    for (int mt = 0; mt < 2; mt++) {
        const __half* qp0 = qkv + (rowbase + q0 + mt * 16 + gid) * QKVD + h * HD;
        const __half* qp1 = qkv + (rowbase + q0 + mt * 16 + gid + 8) * QKVD + h * HD;
        qa[mt][0] = *(const uint4*)(qp0 + 8 * tig);
        qa[mt][1] = *(const uint4*)(qp1 + 8 * tig);
    }

    const int key0 = ((lane >> 3) & 1) * 8 + (lane & 7);
    const int csw  = (key0 >> 1) & 3;
    const int csel = (lane >> 4) & 1;

    const uint32_t skaddr = smem_u32(sk4);
    const uint32_t svaddr = smem_u32(sv4);

    auto issue = [&](int t, int sb) {
#pragma unroll
        for (int it = 0; it < 2; it++) {
            const int idx = tid + 128 * it;
            const int k = idx >> 2, g = idx & 3;
            const __half* base = qkv + (rowbase + t * 64 + k) * QKVD + CDIM + h * HD;
            cp_async16(skaddr + (sb * 256 + k * 4 + g) * 16, base + g * 8);
            cp_async16(svaddr + (sb * 256 + k * 4 + (g ^ ((k >> 1) & 3))) * 16,
                       base + CDIM + g * 8);
        }
        CP_COMMIT();
    };

    issue(0, 0);
    issue(1, 1);

    float lacc[2][4];
    float o[2][4][4];
#pragma unroll
    for (int mt = 0; mt < 2; mt++) {
#pragma unroll
        for (int r = 0; r < 4; r++) lacc[mt][r] = 0.0f;
#pragma unroll
        for (int ni = 0; ni < 4; ni++)
#pragma unroll
            for (int r = 0; r < 4; r++) o[mt][ni][r] = 0.0f;
    }

    const uint32_t ONES = 0x3C003C00u;

    int rb = 0;
    for (int kt = 0; kt < 16; kt++) {
        if (kt + 1 < 16) { CP_WAIT(1); } else { CP_WAIT(0); }
        __syncthreads();
        if (kt + 2 < 16) issue(kt + 2, (rb + 2 >= 3) ? rb - 1 : rb + 2);

        uint4 kb[8];
#pragma unroll
        for (int nj = 0; nj < 8; nj++)
            kb[nj] = sk4[rb][(nj * 8 + gid) * 4 + tig];

        uint32_t pf[2][8][2];
#pragma unroll
        for (int mt = 0; mt < 2; mt++) {
#pragma unroll
            for (int nj = 0; nj < 8; nj++) {
                float s[4];
#pragma unroll
                for (int r = 0; r < 4; r++) s[r] = 0.0f;
                uint32_t af[4], bf[2];
                af[0] = qa[mt][0].x; af[1] = qa[mt][1].x;
                af[2] = qa[mt][0].y; af[3] = qa[mt][1].y;
                bf[0] = kb[nj].x; bf[1] = kb[nj].y;
                mma_f16(s, af, bf);
                af[0] = qa[mt][0].z; af[1] = qa[mt][1].z;
                af[2] = qa[mt][0].w; af[3] = qa[mt][1].w;
                bf[0] = kb[nj].z; bf[1] = kb[nj].w;
                mma_f16(s, af, bf);
                pf[mt][nj][0] = h2ex2(packh2(s[0] * C2LOG, s[1] * C2LOG));
                pf[mt][nj][1] = h2ex2(packh2(s[2] * C2LOG, s[3] * C2LOG));
            }
        }

        const uint32_t vbase = svaddr + rb * 4096 + key0 * 64;
#pragma unroll
        for (int t = 0; t < 4; t++) {
            uint32_t af[2][4];
#pragma unroll
            for (int mt = 0; mt < 2; mt++) {
                af[mt][0] = pf[mt][2 * t][0];
                af[mt][1] = pf[mt][2 * t][1];
                af[mt][2] = pf[mt][2 * t + 1][0];
                af[mt][3] = pf[mt][2 * t + 1][1];
            }
            uint32_t ob[2] = { ONES, ONES };
            mma_f16(lacc[0], af[0], ob);
            mma_f16(lacc[1], af[1], ob);
#pragma unroll
            for (int dh = 0; dh < 2; dh++) {
                uint32_t v0, v1, v2, v3;
                const uint32_t addr = vbase + t * 1024 + (((dh * 2 + csel) ^ csw) * 16);
                ldmx4t(v0, v1, v2, v3, addr);
                uint32_t bf0[2] = { v0, v1 };
                uint32_t bf1[2] = { v2, v3 };
#pragma unroll
                for (int mt = 0; mt < 2; mt++) {
                    mma_f16(o[mt][dh * 2],     af[mt], bf0);
                    mma_f16(o[mt][dh * 2 + 1], af[mt], bf1);
                }
            }
        }
        rb = (rb + 1 == 3) ? 0 : rb + 1;
    }

#pragma unroll
    for (int mt = 0; mt < 2; mt++) {
        const float inv0 = 1.0f / lacc[mt][0];
        const float inv1 = 1.0f / lacc[mt][2];
        __half* op0 = o_out + (rowbase + q0 + mt * 16 + gid) * CDIM + h * HD;
        __half* op1 = o_out + (rowbase + q0 + mt * 16 + gid + 8) * CDIM + h * HD;
#pragma unroll
        for (int ni = 0; ni < 4; ni++) {
            *(uint32_t*)(op0 + ni * 8 + tig * 2) =
                packh2(o[mt][ni][0] * inv0, o[mt][ni][1] * inv0);
            *(uint32_t*)(op1 + ni * 8 + tig * 2) =
                packh2(o[mt][ni][2] * inv1, o[mt][ni][3] * inv1);
        }
    }
}

// ---------------------------------------------------------------------------
// Launch
// ---------------------------------------------------------------------------
extern "C" void kernel_launch(void* const* d_in, const int* in_sizes, int n_in,
                              void* d_out, int out_size)
{
    const float* x    = (const float*)d_in[0];
    const float* Wd   = (const float*)d_in[1];
    const float* Wqkv = (const float*)d_in[2];
    const float* Wup  = (const float*)d_in[3];
    const float* bup  = (const float*)d_in[4];
    float* out = (float*)d_out;

    __half *pqkv16, *po16, *pwdT, *pwqkvT, *pwupT;
    cudaGetSymbolAddress((void**)&pqkv16, g_qkv16);
    cudaGetSymbolAddress((void**)&po16,   g_o16);
    cudaGetSymbolAddress((void**)&pwdT,   g_wdT);
    cudaGetSymbolAddress((void**)&pwqkvT, g_wqkvT);
    cudaGetSymbolAddress((void**)&pwupT,  g_wupT);

    cudaFuncSetAttribute(gemm12_f16, cudaFuncAttributeMaxDynamicSharedMemorySize,
                         G1_SMEM_BYTES);
    cudaFuncSetAttribute(gemm_f16<false>,
                         cudaFuncAttributeMaxDynamicSharedMemorySize, GEMM_SMEM_BYTES);

    // prologue: fused weight transposes (one launch)
    transpose_all<<<832, dim3(32, 8)>>>(Wd, Wqkv, Wup, pwdT, pwqkvT, pwupT);

    // fused GEMM1+GEMM2: x -> h(smem) -> qkv
    gemm12_f16<<<M_TOTAL / 128, 256, G1_SMEM_BYTES>>>(x, pwdT, pwqkvT, pqkv16);

    // attention
    attn_f16<<<BATCH * HEADS * CUT * (BLKTOK / 128), 128>>>(pqkv16, po16);

    // GEMM3: out = o16 @ Wup + bup (persistent, fp32 out)
    gemm_f16<false><<<296, 256, GEMM_SMEM_BYTES>>>(po16, pwupT, bup, out,
                                                   M_TOTAL, INCH, CDIM);
}

// round 17
// speedup vs baseline: 1.0976x; 1.0369x over previous
#include <cuda_runtime.h>
#include <cuda_fp16.h>
#include <stdint.h>
#include <math.h>

// ---------------------------------------------------------------------------
// Problem constants
// ---------------------------------------------------------------------------
#define BATCH   4
#define NTOK    4096
#define INCH    1280
#define CDIM    256
#define QKVD    768
#define HEADS   8
#define HD      32
#define CUT     4
#define BLKTOK  1024
#define M_TOTAL (BATCH*NTOK)
#define SCALE_F 0.07905694150420949f   // 160^-0.5
#define C2LOG   (SCALE_F * 1.4426950408889634f)   // SCALE * log2(e)

// ---------------------------------------------------------------------------
// Scratch
// ---------------------------------------------------------------------------
__device__ __half g_qkv16[M_TOTAL * QKVD];
__device__ __half g_o16[M_TOTAL * CDIM];
__device__ __half g_wdT[CDIM * INCH];
__device__ __half g_wqkvT[QKVD * CDIM];
__device__ __half g_wupT[INCH * CDIM];

// ---------------------------------------------------------------------------
// helpers
// ---------------------------------------------------------------------------
__device__ __forceinline__ void mma_f16(float* d, const uint32_t* a, const uint32_t* b) {
    asm volatile(
        "mma.sync.aligned.m16n8k16.row.col.f32.f16.f16.f32 "
        "{%0,%1,%2,%3}, {%4,%5,%6,%7}, {%8,%9}, {%0,%1,%2,%3};"
        : "+f"(d[0]), "+f"(d[1]), "+f"(d[2]), "+f"(d[3])
        : "r"(a[0]), "r"(a[1]), "r"(a[2]), "r"(a[3]), "r"(b[0]), "r"(b[1]));
}
__device__ __forceinline__ uint32_t smem_u32(const void* p) {
    uint32_t a;
    asm("{ .reg .u64 t; cvta.to.shared.u64 t, %1; cvt.u32.u64 %0, t; }" : "=r"(a) : "l"(p));
    return a;
}
__device__ __forceinline__ void cp_async16(uint32_t dst, const void* src) {
    asm volatile("cp.async.cg.shared.global [%0], [%1], 16;" :: "r"(dst), "l"(src));
}
#define CP_COMMIT() asm volatile("cp.async.commit_group;" ::: "memory")
#define CP_WAIT(n)  asm volatile("cp.async.wait_group %0;" :: "n"(n) : "memory")

__device__ __forceinline__ uint32_t packh2(float lo, float hi) {
    __half2 h = __floats2half2_rn(lo, hi);
    return *(uint32_t*)&h;
}
__device__ __forceinline__ uint32_t h2ex2(uint32_t h2) {
    uint32_t r;
    asm("ex2.approx.f16x2 %0, %1;" : "=r"(r) : "r"(h2));
    return r;
}
__device__ __forceinline__ void ldmx4t(uint32_t& v0, uint32_t& v1, uint32_t& v2,
                                       uint32_t& v3, uint32_t addr) {
    asm volatile("ldmatrix.sync.aligned.m8n8.x4.trans.shared.b16 {%0,%1,%2,%3}, [%4];"
                 : "=r"(v0), "=r"(v1), "=r"(v2), "=r"(v3) : "r"(addr));
}

// ---------------------------------------------------------------------------
// Fused weight transposes fp32 -> fp16 K-major (one launch, 3 segments)
// ---------------------------------------------------------------------------
__global__ void transpose_all(const float* __restrict__ Wd,
                              const float* __restrict__ Wqkv,
                              const float* __restrict__ Wup,
                              __half* __restrict__ wdT,
                              __half* __restrict__ wqkvT,
                              __half* __restrict__ wupT)
{
    __shared__ float t[32][33];
    const int bx = blockIdx.x;
    const float* W; __half* WT; int K, N, gx, base;
    if (bx < 320)      { W = Wd;   WT = wdT;   K = INCH; N = CDIM; gx = 40; base = 0; }
    else if (bx < 512) { W = Wqkv; WT = wqkvT; K = CDIM; N = QKVD; gx = 8;  base = 320; }
    else               { W = Wup;  WT = wupT;  K = CDIM; N = INCH; gx = 8;  base = 512; }
    const int i = bx - base;
    const int kb = (i % gx) * 32, nb = (i / gx) * 32;
    const int tx = threadIdx.x, ty = threadIdx.y;
#pragma unroll
    for (int r = 0; r < 4; r++)
        t[ty + 8 * r][tx] = W[(size_t)(kb + ty + 8 * r) * N + nb + tx];
    __syncthreads();
#pragma unroll
    for (int r = 0; r < 4; r++)
        WT[(size_t)(nb + ty + 8 * r) * K + kb + tx] = __float2half_rn(t[tx][ty + 8 * r]);
}

// ---------------------------------------------------------------------------
// Fused GEMM1+GEMM2 (proven R16): per CTA (128 rows):
//   phase1: h(128x256) = x(fp32)@WdT, h -> SMEM only
//   phase2: qkv(128x768) = h(smem) @ WqkvT, 6 N-chunks of 128, B streamed
// ---------------------------------------------------------------------------
#define A1STRIDE 36
#define A1BUF (128 * A1STRIDE)
#define B1BUF (256 * 16)
#define G1_SMEM_BYTES (3 * (A1BUF + B1BUF) * 4)   // 104448
#define H_WORDS 16384
#define B2RING  (H_WORDS)
#define B2BUF   2048

__global__ void __launch_bounds__(256, 1)
gemm12_f16(const float* __restrict__ A, const __half* __restrict__ BT1,
           const __half* __restrict__ BT2, __half* __restrict__ C)
{
    extern __shared__ uint32_t smem[];
    float*    As = (float*)smem;
    uint32_t* Bs = smem + 3 * A1BUF;

    const int tid  = threadIdx.x;
    const int wid  = tid >> 5;
    const int lane = tid & 31;
    const int gid  = lane >> 2;
    const int tig  = lane & 3;
    const int wm   = wid >> 2;
    const int wn   = wid & 3;
    const int rowBase = blockIdx.x * 128;

    // ======================= PHASE 1: h = x @ Wd =======================
    {
        const int K = INCH;
        float acc[4][8][4];
#pragma unroll
        for (int mi = 0; mi < 4; mi++)
#pragma unroll
            for (int ni = 0; ni < 8; ni++)
#pragma unroll
                for (int r = 0; r < 4; r++) acc[mi][ni][r] = 0.0f;

        const uint32_t asBase = smem_u32(As);
        const uint32_t bsBase = smem_u32(Bs);
        const int nst = K / 32;

        auto issue = [&](int st, int sb) {
            const int kt = st * 32;
            const uint32_t ab = asBase + (sb * A1BUF) * 4;
            const uint32_t bb = bsBase + (sb * B1BUF) * 4;
#pragma unroll
            for (int it = 0; it < 4; it++) {
                const int ch = tid + 256 * it;
                const int ar = ch >> 3, ag = ch & 7;
                cp_async16(ab + (ar * A1STRIDE + ag * 4) * 4,
                           &A[(size_t)(rowBase + ar) * K + kt + ag * 4]);
                const int br = ch >> 2, bg = ch & 3;
                cp_async16(bb + (br * 16 + bg * 4) * 4,
                           &BT1[(size_t)br * K + kt + bg * 8]);
            }
            CP_COMMIT();
        };

        issue(0, 0);
        issue(1, 1);

        int rb = 0;
        for (int st = 0; st < nst; st++) {
            if (st + 1 < nst) { CP_WAIT(1); } else { CP_WAIT(0); }
            __syncthreads();
            if (st + 2 < nst) issue(st + 2, (rb + 2 >= 3) ? rb - 1 : rb + 2);

            const float* Ab = As + rb * A1BUF;
            const uint4* B4 = (const uint4*)(Bs + rb * B1BUF);

            uint4 a0[4], a1[4];
#pragma unroll
            for (int mi = 0; mi < 4; mi++) {
                const int r0 = wm * 64 + mi * 16 + gid;
                const float4 f0 = *(const float4*)(Ab + r0 * A1STRIDE + tig * 8);
                const float4 f1 = *(const float4*)(Ab + r0 * A1STRIDE + tig * 8 + 4);
                const float4 g0 = *(const float4*)(Ab + (r0 + 8) * A1STRIDE + tig * 8);
                const float4 g1 = *(const float4*)(Ab + (r0 + 8) * A1STRIDE + tig * 8 + 4);
                a0[mi].x = packh2(f0.x, f0.y); a0[mi].y = packh2(f0.z, f0.w);
                a0[mi].z = packh2(f1.x, f1.y); a0[mi].w = packh2(f1.z, f1.w);
                a1[mi].x = packh2(g0.x, g0.y); a1[mi].y = packh2(g0.z, g0.w);
                a1[mi].z = packh2(g1.x, g1.y); a1[mi].w = packh2(g1.z, g1.w);
            }
#pragma unroll
            for (int ni = 0; ni < 8; ni++) {
                const int c0 = wn * 64 + ni * 8 + gid;
                const uint4 bv = B4[c0 * 4 + tig];
#pragma unroll
                for (int mi = 0; mi < 4; mi++) {
                    uint32_t af[4], bf[2];
                    af[0] = a0[mi].x; af[1] = a1[mi].x;
                    af[2] = a0[mi].y; af[3] = a1[mi].y;
                    bf[0] = bv.x; bf[1] = bv.y;
                    mma_f16(acc[mi][ni], af, bf);
                    af[0] = a0[mi].z; af[1] = a1[mi].z;
                    af[2] = a0[mi].w; af[3] = a1[mi].w;
                    bf[0] = bv.z; bf[1] = bv.w;
                    mma_f16(acc[mi][ni], af, bf);
                }
            }
            rb = (rb + 1 == 3) ? 0 : rb + 1;
        }

        __syncthreads();
#pragma unroll
        for (int mi = 0; mi < 4; mi++) {
#pragma unroll
            for (int ni = 0; ni < 8; ni++) {
                const int row0 = wm * 64 + mi * 16 + gid;
                const int col  = wn * 64 + ni * 8 + tig * 2;
                const int w    = col >> 1;
                const int st   = w >> 4;
                const int wi   = w & 15;
                smem[st * 2048 + row0 * 16 + wi] = packh2(acc[mi][ni][0], acc[mi][ni][1]);
                smem[st * 2048 + (row0 + 8) * 16 + wi] = packh2(acc[mi][ni][2], acc[mi][ni][3]);
            }
        }
    }

    // ======================= PHASE 2: qkv = h @ Wqkv =======================
    {
        const int K = CDIM;
        const uint32_t ringB = smem_u32(smem + B2RING);

        auto issue2 = [&](int gs, int sb) {
            const int chunk = gs >> 3;
            const int st    = gs & 7;
            const int kt    = st * 32;
            const uint32_t bb = ringB + (sb * B2BUF) * 4;
#pragma unroll
            for (int it = 0; it < 2; it++) {
                const int r = (tid >> 2) + 64 * it;
                const int g = tid & 3;
                cp_async16(bb + (r * 16 + g * 4) * 4,
                           &BT2[(size_t)(chunk * 128 + r) * K + kt + g * 8]);
            }
            CP_COMMIT();
        };

        issue2(0, 0);
        issue2(1, 1);

        float acc2[4][4][4];
#pragma unroll
        for (int mi = 0; mi < 4; mi++)
#pragma unroll
            for (int ni = 0; ni < 4; ni++)
#pragma unroll
                for (int r = 0; r < 4; r++) acc2[mi][ni][r] = 0.0f;

        const uint4* hA4 = (const uint4*)smem;

        int rb = 0;
        for (int gs = 0; gs < 48; gs++) {
            const int chunk = gs >> 3;
            const int st    = gs & 7;
            if (gs + 1 < 48) { CP_WAIT(1); } else { CP_WAIT(0); }
            __syncthreads();
            if (gs + 2 < 48) issue2(gs + 2, (rb + 2 >= 3) ? rb - 1 : rb + 2);

            const uint4* B4 = (const uint4*)(smem + B2RING + rb * B2BUF);

            uint4 bv[4];
#pragma unroll
            for (int ni = 0; ni < 4; ni++)
                bv[ni] = B4[(wn * 32 + ni * 8 + gid) * 4 + tig];
#pragma unroll
            for (int mi = 0; mi < 4; mi++) {
                const int r0 = wm * 64 + mi * 16 + gid;
                const uint4 a0 = hA4[st * 512 + r0 * 4 + tig];
                const uint4 a1 = hA4[st * 512 + (r0 + 8) * 4 + tig];
#pragma unroll
                for (int ni = 0; ni < 4; ni++) {
                    uint32_t af[4], bf[2];
                    af[0] = a0.x; af[1] = a1.x;
                    af[2] = a0.y; af[3] = a1.y;
                    bf[0] = bv[ni].x; bf[1] = bv[ni].y;
                    mma_f16(acc2[mi][ni], af, bf);
                    af[0] = a0.z; af[1] = a1.z;
                    af[2] = a0.w; af[3] = a1.w;
                    bf[0] = bv[ni].z; bf[1] = bv[ni].w;
                    mma_f16(acc2[mi][ni], af, bf);
                }
            }

            if (st == 7) {
#pragma unroll
                for (int mi = 0; mi < 4; mi++) {
#pragma unroll
                    for (int ni = 0; ni < 4; ni++) {
                        const int row0 = rowBase + wm * 64 + mi * 16 + gid;
                        const int col  = chunk * 128 + wn * 32 + ni * 8 + tig * 2;
                        *(uint32_t*)&C[(size_t)row0 * QKVD + col] =
                            packh2(acc2[mi][ni][0], acc2[mi][ni][1]);
                        *(uint32_t*)&C[(size_t)(row0 + 8) * QKVD + col] =
                            packh2(acc2[mi][ni][2], acc2[mi][ni][3]);
#pragma unroll
                        for (int r = 0; r < 4; r++) acc2[mi][ni][r] = 0.0f;
                    }
                }
            }
            rb = (rb + 1 == 3) ? 0 : rb + 1;
        }
    }
}

// ---------------------------------------------------------------------------
// GEMM3 with resident B column: out[M,1280] = o16 @ WupT + bup.
// CTA pins one of 10 column tiles; B slab (128x256 fp16 = 64KB) loaded once
// into smem [8 st][128][16 b32]; row tiles stream only A through a 3-slot
// ring. 256 threads, 8 warps (2x4), warp 64x32. grid = 296, 2 CTAs/SM.
// ---------------------------------------------------------------------------
#define G3_BWORDS 16384
#define G3_ABUF   2048
#define G3_SMEM_BYTES ((G3_BWORDS + 3 * G3_ABUF) * 4)   // 90112

__global__ void __launch_bounds__(256, 2)
gemm3_f16(const __half* __restrict__ A, const __half* __restrict__ BT,
          const float* __restrict__ bias, float* __restrict__ C)
{
    extern __shared__ uint32_t smem[];

    const int tid  = threadIdx.x;
    const int wid  = tid >> 5;
    const int lane = tid & 31;
    const int gid  = lane >> 2;
    const int tig  = lane & 3;
    const int wm   = wid >> 2;
    const int wn   = wid & 3;
    const int K = CDIM;   // 256

    const int col10 = blockIdx.x % 10;
    const int cin   = blockIdx.x / 10;                 // 0..29
    const int nCin  = 29 + (col10 < 6 ? 1 : 0);        // 6*30 + 4*29 = 296
    const int colBase = col10 * 128;

    const uint32_t sB = smem_u32(smem);
    const uint32_t sA = smem_u32(smem + G3_BWORDS);

    // ---- load resident B (one commit group; oldest, so any wait covers it)
#pragma unroll
    for (int i = 0; i < 16; i++) {
        const int idx = tid + 256 * i;
        const int g = idx & 3, r = (idx >> 2) & 127, st = idx >> 9;
        cp_async16(sB + (st * 2048 + r * 16 + g * 4) * 4,
                   &BT[(size_t)(colBase + r) * K + st * 32 + g * 8]);
    }
    CP_COMMIT();

    const int fr = tid >> 2;
    const int fg = tid & 3;

    auto issueA = [&](int rowBase, int st, int sb) {
        const int kt = st * 32;
        const uint32_t ab = sA + (sb * G3_ABUF) * 4;
#pragma unroll
        for (int it = 0; it < 2; it++) {
            const int r = fr + 64 * it;
            cp_async16(ab + (r * 16 + fg * 4) * 4,
                       &A[(size_t)(rowBase + r) * K + kt + fg * 8]);
        }
        CP_COMMIT();
    };

    const uint4* Bres = (const uint4*)smem;

    for (int rt = cin; rt < 128; rt += nCin) {
        const int rowBase = rt * 128;
        __syncthreads();   // all warps done with previous tile's ring reads
        issueA(rowBase, 0, 0);
        issueA(rowBase, 1, 1);

        float acc[4][4][4];
#pragma unroll
        for (int mi = 0; mi < 4; mi++)
#pragma unroll
            for (int ni = 0; ni < 4; ni++)
#pragma unroll
                for (int r = 0; r < 4; r++) acc[mi][ni][r] = 0.0f;

        int rb = 0;
        for (int st = 0; st < 8; st++) {
            if (st + 1 < 8) { CP_WAIT(1); } else { CP_WAIT(0); }
            __syncthreads();
            if (st + 2 < 8) issueA(rowBase, st + 2, (rb + 2 >= 3) ? rb - 1 : rb + 2);

            const uint4* A4 = (const uint4*)(smem + G3_BWORDS + rb * G3_ABUF);

            uint4 bv[4];
#pragma unroll
            for (int ni = 0; ni < 4; ni++)
                bv[ni] = Bres[st * 512 + (wn * 32 + ni * 8 + gid) * 4 + tig];
#pragma unroll
            for (int mi = 0; mi < 4; mi++) {
                const int r0 = wm * 64 + mi * 16 + gid;
                const uint4 a0 = A4[r0 * 4 + tig];
                const uint4 a1 = A4[(r0 + 8) * 4 + tig];
#pragma unroll
                for (int ni = 0; ni < 4; ni++) {
                    uint32_t af[4], bf[2];
                    af[0] = a0.x; af[1] = a1.x;
                    af[2] = a0.y; af[3] = a1.y;
                    bf[0] = bv[ni].x; bf[1] = bv[ni].y;
                    mma_f16(acc[mi][ni], af, bf);
                    af[0] = a0.z; af[1] = a1.z;
                    af[2] = a0.w; af[3] = a1.w;
                    bf[0] = bv[ni].z; bf[1] = bv[ni].w;
                    mma_f16(acc[mi][ni], af, bf);
                }
            }
            rb = (rb + 1 == 3) ? 0 : rb + 1;
        }

        // ---- epilogue (fp32 + bias)
#pragma unroll
        for (int mi = 0; mi < 4; mi++) {
#pragma unroll
            for (int ni = 0; ni < 4; ni++) {
                const int row0 = rowBase + wm * 64 + mi * 16 + gid;
                const int col  = colBase + wn * 32 + ni * 8 + tig * 2;
                const float b0 = bias[col];
                const float b1 = bias[col + 1];
                float2 v0, v1;
                v0.x = acc[mi][ni][0] + b0; v0.y = acc[mi][ni][1] + b1;
                v1.x = acc[mi][ni][2] + b0; v1.y = acc[mi][ni][3] + b1;
                *(float2*)&C[(size_t)row0 * INCH + col] = v0;
                *(float2*)&C[(size_t)(row0 + 8) * INCH + col] = v1;
            }
        }
    }
}

// ---------------------------------------------------------------------------
// fp16 flash attention v4 (proven R14, 49.2us): no online max, direct ex2.
// ---------------------------------------------------------------------------
__global__ void __launch_bounds__(128, 2)
attn_f16(const __half* __restrict__ qkv, __half* __restrict__ o_out)
{
    __shared__ uint4 sk4[3][256];
    __shared__ uint4 sv4[3][256];

    const int bx = blockIdx.x;
    const int qt = bx & 7;
    const int c  = (bx >> 3) & 3;
    const int h  = (bx >> 5) & 7;
    const int b  = bx >> 8;

    const int tid  = threadIdx.x;
    const int wid  = tid >> 5;
    const int lane = tid & 31;
    const int gid  = lane >> 2;
    const int tig  = lane & 3;

    const size_t rowbase = (size_t)b * NTOK + (size_t)c * BLKTOK;
    const int q0 = qt * 128 + wid * 32;

    uint4 qa[2][2];
#pragma unroll
    for (int mt = 0; mt < 2; mt++) {
        const __half* qp0 = qkv + (rowbase + q0 + mt * 16 + gid) * QKVD + h * HD;
        const __half* qp1 = qkv + (rowbase + q0 + mt * 16 + gid + 8) * QKVD + h * HD;
        qa[mt][0] = *(const uint4*)(qp0 + 8 * tig);
        qa[mt][1] = *(const uint4*)(qp1 + 8 * tig);
    }

    const int key0 = ((lane >> 3) & 1) * 8 + (lane & 7);
    const int csw  = (key0 >> 1) & 3;
    const int csel = (lane >> 4) & 1;

    const uint32_t skaddr = smem_u32(sk4);
    const uint32_t svaddr = smem_u32(sv4);

    auto issue = [&](int t, int sb) {
#pragma unroll
        for (int it = 0; it < 2; it++) {
            const int idx = tid + 128 * it;
            const int k = idx >> 2, g = idx & 3;
            const __half* base = qkv + (rowbase + t * 64 + k) * QKVD + CDIM + h * HD;
            cp_async16(skaddr + (sb * 256 + k * 4 + g) * 16, base + g * 8);
            cp_async16(svaddr + (sb * 256 + k * 4 + (g ^ ((k >> 1) & 3))) * 16,
                       base + CDIM + g * 8);
        }
        CP_COMMIT();
    };

    issue(0, 0);
    issue(1, 1);

    float lacc[2][4];
    float o[2][4][4];
#pragma unroll
    for (int mt = 0; mt < 2; mt++) {
#pragma unroll
        for (int r = 0; r < 4; r++) lacc[mt][r] = 0.0f;
#pragma unroll
        for (int ni = 0; ni < 4; ni++)
#pragma unroll
            for (int r = 0; r < 4; r++) o[mt][ni][r] = 0.0f;
    }

    const uint32_t ONES = 0x3C003C00u;

    int rb = 0;
    for (int kt = 0; kt < 16; kt++) {
        if (kt + 1 < 16) { CP_WAIT(1); } else { CP_WAIT(0); }
        __syncthreads();
        if (kt + 2 < 16) issue(kt + 2, (rb + 2 >= 3) ? rb - 1 : rb + 2);

        uint4 kb[8];
#pragma unroll
        for (int nj = 0; nj < 8; nj++)
            kb[nj] = sk4[rb][(nj * 8 + gid) * 4 + tig];

        uint32_t pf[2][8][2];
#pragma unroll
        for (int mt = 0; mt < 2; mt++) {
#pragma unroll
            for (int nj = 0; nj < 8; nj++) {
                float s[4];
#pragma unroll
                for (int r = 0; r < 4; r++) s[r] = 0.0f;
                uint32_t af[4], bf[2];
                af[0] = qa[mt][0].x; af[1] = qa[mt][1].x;
                af[2] = qa[mt][0].y; af[3] = qa[mt][1].y;
                bf[0] = kb[nj].x; bf[1] = kb[nj].y;
                mma_f16(s, af, bf);
                af[0] = qa[mt][0].z; af[1] = qa[mt][1].z;
                af[2] = qa[mt][0].w; af[3] = qa[mt][1].w;
                bf[0] = kb[nj].z; bf[1] = kb[nj].w;
                mma_f16(s, af, bf);
                pf[mt][nj][0] = h2ex2(packh2(s[0] * C2LOG, s[1] * C2LOG));
                pf[mt][nj][1] = h2ex2(packh2(s[2] * C2LOG, s[3] * C2LOG));
            }
        }

        const uint32_t vbase = svaddr + rb * 4096 + key0 * 64;
#pragma unroll
        for (int t = 0; t < 4; t++) {
            uint32_t af[2][4];
#pragma unroll
            for (int mt = 0; mt < 2; mt++) {
                af[mt][0] = pf[mt][2 * t][0];
                af[mt][1] = pf[mt][2 * t][1];
                af[mt][2] = pf[mt][2 * t + 1][0];
                af[mt][3] = pf[mt][2 * t + 1][1];
            }
            uint32_t ob[2] = { ONES, ONES };
            mma_f16(lacc[0], af[0], ob);
            mma_f16(lacc[1], af[1], ob);
#pragma unroll
            for (int dh = 0; dh < 2; dh++) {
                uint32_t v0, v1, v2, v3;
                const uint32_t addr = vbase + t * 1024 + (((dh * 2 + csel) ^ csw) * 16);
                ldmx4t(v0, v1, v2, v3, addr);
                uint32_t bf0[2] = { v0, v1 };
                uint32_t bf1[2] = { v2, v3 };
#pragma unroll
                for (int mt = 0; mt < 2; mt++) {
                    mma_f16(o[mt][dh * 2],     af[mt], bf0);
                    mma_f16(o[mt][dh * 2 + 1], af[mt], bf1);
                }
            }
        }
        rb = (rb + 1 == 3) ? 0 : rb + 1;
    }

#pragma unroll
    for (int mt = 0; mt < 2; mt++) {
        const float inv0 = 1.0f / lacc[mt][0];
        const float inv1 = 1.0f / lacc[mt][2];
        __half* op0 = o_out + (rowbase + q0 + mt * 16 + gid) * CDIM + h * HD;
        __half* op1 = o_out + (rowbase + q0 + mt * 16 + gid + 8) * CDIM + h * HD;
#pragma unroll
        for (int ni = 0; ni < 4; ni++) {
            *(uint32_t*)(op0 + ni * 8 + tig * 2) =
                packh2(o[mt][ni][0] * inv0, o[mt][ni][1] * inv0);
            *(uint32_t*)(op1 + ni * 8 + tig * 2) =
                packh2(o[mt][ni][2] * inv1, o[mt][ni][3] * inv1);
        }
    }
}

// ---------------------------------------------------------------------------
// Launch
// ---------------------------------------------------------------------------
extern "C" void kernel_launch(void* const* d_in, const int* in_sizes, int n_in,
                              void* d_out, int out_size)
{
    const float* x    = (const float*)d_in[0];
    const float* Wd   = (const float*)d_in[1];
    const float* Wqkv = (const float*)d_in[2];
    const float* Wup  = (const float*)d_in[3];
    const float* bup  = (const float*)d_in[4];
    float* out = (float*)d_out;

    __half *pqkv16, *po16, *pwdT, *pwqkvT, *pwupT;
    cudaGetSymbolAddress((void**)&pqkv16, g_qkv16);
    cudaGetSymbolAddress((void**)&po16,   g_o16);
    cudaGetSymbolAddress((void**)&pwdT,   g_wdT);
    cudaGetSymbolAddress((void**)&pwqkvT, g_wqkvT);
    cudaGetSymbolAddress((void**)&pwupT,  g_wupT);

    cudaFuncSetAttribute(gemm12_f16, cudaFuncAttributeMaxDynamicSharedMemorySize,
                         G1_SMEM_BYTES);
    cudaFuncSetAttribute(gemm3_f16, cudaFuncAttributeMaxDynamicSharedMemorySize,
                         G3_SMEM_BYTES);

    // prologue: fused weight transposes (one launch)
    transpose_all<<<832, dim3(32, 8)>>>(Wd, Wqkv, Wup, pwdT, pwqkvT, pwupT);

    // fused GEMM1+GEMM2: x -> h(smem) -> qkv
    gemm12_f16<<<M_TOTAL / 128, 256, G1_SMEM_BYTES>>>(x, pwdT, pwqkvT, pqkv16);

    // attention
    attn_f16<<<BATCH * HEADS * CUT * (BLKTOK / 128), 128>>>(pqkv16, po16);

    // GEMM3: out = o16 @ Wup + bup (B-resident columns, fp32 out)
    gemm3_f16<<<296, 256, G3_SMEM_BYTES>>>(po16, pwupT, bup, out);
}